// round 3
// baseline (speedup 1.0000x reference)
#include <cuda_runtime.h>

#define TT   8192
#define HID  768
#define G4   3072          // 4*HID
#define D2   1536          // 2*HID
#define EE   16384
#define NG   2048
#define NSENT 32

#define NBD      64        // blocks per direction
#define UPB      12        // hidden units per block
#define RTHREADS 384       // 12 warps: one warp per unit

// ---- output layout in d_out (flat float32, tuple order) ----
#define OUT_OFF  0
#define SENT_OFF (TT*D2)
#define COPY_OFF (SENT_OFF + NSENT*D2)
#define HN_OFF   (COPY_OFF + NG*D2)
#define CN_OFF   (HN_OFF + 4*HID)

typedef unsigned long long ull;

// ---- scratch ----
__device__ float g_pre[2ull * TT * G4];
__device__ float g_x1[(size_t)TT * D2];
__device__ ull   g_hb[2][2][HID];      // [parity][dir][unit]: (tag<<32)|bits(h)

// ---------------------------------------------------------------------------
__device__ __forceinline__ ull ld_relaxed(const ull* p) {
    ull v;
    asm volatile("ld.relaxed.gpu.global.b64 %0, [%1];" : "=l"(v) : "l"(p) : "memory");
    return v;
}
__device__ __forceinline__ void st_relaxed(ull* p, ull v) {
    asm volatile("st.relaxed.gpu.global.b64 [%0], %1;" :: "l"(p), "l"(v) : "memory");
}
__device__ __forceinline__ ull ffma2(ull a, ull b, ull c) {
    ull d;
    asm("fma.rn.f32x2 %0, %1, %2, %3;" : "=l"(d) : "l"(a), "l"(b), "l"(c));
    return d;
}
union F2U { float2 f; ull u; };

__global__ void init_kernel() {
    int tid = blockIdx.x * blockDim.x + threadIdx.x;
    if (tid < 2 * 2 * HID) ((ull*)g_hb)[tid] = 0ull;
}

// ---------------------------------------------------------------------------
// Split-TF32 tensor-core GEMM: pre = X(MxK) @ W^T + bias -> g_pre[dir][t][4H]
// D = Ah*Bh + Al*Bh + Ah*Bl  (error ~2^-22, i.e. fp32-equivalent)
// Block 128x128x16, 8 warps as 4(m) x 2(n); warp tile 32x64 = 2x8 m16n8k8 mmas.
#define SPAD 136

__device__ __forceinline__ void mma_tf32(float* d, const unsigned* a, const unsigned* b) {
    asm volatile(
        "mma.sync.aligned.m16n8k8.row.col.f32.tf32.tf32.f32 "
        "{%0,%1,%2,%3}, {%4,%5,%6,%7}, {%8,%9}, {%0,%1,%2,%3};"
        : "+f"(d[0]), "+f"(d[1]), "+f"(d[2]), "+f"(d[3])
        : "r"(a[0]), "r"(a[1]), "r"(a[2]), "r"(a[3]), "r"(b[0]), "r"(b[1]));
}
__device__ __forceinline__ void cvt_split(float v, float& hi, float& lo) {
    unsigned uh, ul;
    asm("cvt.rna.tf32.f32 %0, %1;" : "=r"(uh) : "f"(v));
    hi = __uint_as_float(uh);
    float fl = v - hi;                 // exact in fp32
    asm("cvt.rna.tf32.f32 %0, %1;" : "=r"(ul) : "f"(fl));
    lo = __uint_as_float(ul);
}

__global__ __launch_bounds__(256, 1) void gemm_pre_tc(
    const float* __restrict__ X,   // nullptr -> g_x1
    const float* __restrict__ W,   // (6144, K)
    const float* __restrict__ bias,
    int K)
{
    if (X == nullptr) X = g_x1;

    __shared__ float Ahs[16][SPAD], Als[16][SPAD];
    __shared__ float Bhs[16][SPAD], Bls[16][SPAD];

    int tid  = threadIdx.x;
    int warp = tid >> 5, lane = tid & 31;
    int g    = lane >> 2, tig = lane & 3;
    int wm   = warp >> 1, wn = warp & 1;
    int m0 = blockIdx.y * 128, n0 = blockIdx.x * 128;

    int sr  = tid & 127;           // staging row
    int skq = (tid >> 7) * 8;      // staging k offset (0 or 8)

    const float* Ap = X + (size_t)(m0 + sr) * K + skq;
    const float* Bp = W + (size_t)(n0 + sr) * K + skq;

    float acc[2][8][4];
    #pragma unroll
    for (int i = 0; i < 2; i++)
        #pragma unroll
        for (int jn = 0; jn < 8; jn++)
            #pragma unroll
            for (int q = 0; q < 4; q++) acc[i][jn][q] = 0.f;

    float4 av0 = *(const float4*)(Ap);
    float4 av1 = *(const float4*)(Ap + 4);
    float4 bv0 = *(const float4*)(Bp);
    float4 bv1 = *(const float4*)(Bp + 4);

    for (int k0 = 0; k0 < K; k0 += 16) {
        __syncthreads();   // previous tile's consumers done
        {
            float h, l;
            cvt_split(av0.x, h, l); Ahs[skq+0][sr] = h; Als[skq+0][sr] = l;
            cvt_split(av0.y, h, l); Ahs[skq+1][sr] = h; Als[skq+1][sr] = l;
            cvt_split(av0.z, h, l); Ahs[skq+2][sr] = h; Als[skq+2][sr] = l;
            cvt_split(av0.w, h, l); Ahs[skq+3][sr] = h; Als[skq+3][sr] = l;
            cvt_split(av1.x, h, l); Ahs[skq+4][sr] = h; Als[skq+4][sr] = l;
            cvt_split(av1.y, h, l); Ahs[skq+5][sr] = h; Als[skq+5][sr] = l;
            cvt_split(av1.z, h, l); Ahs[skq+6][sr] = h; Als[skq+6][sr] = l;
            cvt_split(av1.w, h, l); Ahs[skq+7][sr] = h; Als[skq+7][sr] = l;
            cvt_split(bv0.x, h, l); Bhs[skq+0][sr] = h; Bls[skq+0][sr] = l;
            cvt_split(bv0.y, h, l); Bhs[skq+1][sr] = h; Bls[skq+1][sr] = l;
            cvt_split(bv0.z, h, l); Bhs[skq+2][sr] = h; Bls[skq+2][sr] = l;
            cvt_split(bv0.w, h, l); Bhs[skq+3][sr] = h; Bls[skq+3][sr] = l;
            cvt_split(bv1.x, h, l); Bhs[skq+4][sr] = h; Bls[skq+4][sr] = l;
            cvt_split(bv1.y, h, l); Bhs[skq+5][sr] = h; Bls[skq+5][sr] = l;
            cvt_split(bv1.z, h, l); Bhs[skq+6][sr] = h; Bls[skq+6][sr] = l;
            cvt_split(bv1.w, h, l); Bhs[skq+7][sr] = h; Bls[skq+7][sr] = l;
        }
        __syncthreads();
        if (k0 + 16 < K) {          // prefetch next tile (overlaps mma)
            av0 = *(const float4*)(Ap + k0 + 16);
            av1 = *(const float4*)(Ap + k0 + 20);
            bv0 = *(const float4*)(Bp + k0 + 16);
            bv1 = *(const float4*)(Bp + k0 + 20);
        }
        #pragma unroll
        for (int ks = 0; ks < 16; ks += 8) {
            unsigned ah[2][4], al[2][4];
            #pragma unroll
            for (int mt = 0; mt < 2; mt++) {
                int rA = wm * 32 + mt * 16 + g;
                ah[mt][0] = __float_as_uint(Ahs[ks+tig  ][rA]);
                ah[mt][1] = __float_as_uint(Ahs[ks+tig  ][rA+8]);
                ah[mt][2] = __float_as_uint(Ahs[ks+tig+4][rA]);
                ah[mt][3] = __float_as_uint(Ahs[ks+tig+4][rA+8]);
                al[mt][0] = __float_as_uint(Als[ks+tig  ][rA]);
                al[mt][1] = __float_as_uint(Als[ks+tig  ][rA+8]);
                al[mt][2] = __float_as_uint(Als[ks+tig+4][rA]);
                al[mt][3] = __float_as_uint(Als[ks+tig+4][rA+8]);
            }
            #pragma unroll
            for (int nt = 0; nt < 8; nt++) {
                int cB = wn * 64 + nt * 8 + g;
                unsigned bh[2], bl[2];
                bh[0] = __float_as_uint(Bhs[ks+tig  ][cB]);
                bh[1] = __float_as_uint(Bhs[ks+tig+4][cB]);
                bl[0] = __float_as_uint(Bls[ks+tig  ][cB]);
                bl[1] = __float_as_uint(Bls[ks+tig+4][cB]);
                #pragma unroll
                for (int mt = 0; mt < 2; mt++) {
                    mma_tf32(acc[mt][nt], ah[mt], bh);
                    mma_tf32(acc[mt][nt], al[mt], bh);
                    mma_tf32(acc[mt][nt], ah[mt], bl);
                }
            }
        }
    }

    // epilogue: n -> (dir, gate-row), m -> t
    int d = (n0 >= G4) ? 1 : 0;
    float* dst = g_pre + (size_t)d * TT * G4;
    int rb = n0 - d * G4 + wn * 64;
    #pragma unroll
    for (int nt = 0; nt < 8; nt++) {
        int r  = rb + nt * 8 + 2 * tig;
        float bs0 = bias[n0 + wn * 64 + nt * 8 + 2 * tig];
        float bs1 = bias[n0 + wn * 64 + nt * 8 + 2 * tig + 1];
        #pragma unroll
        for (int mt = 0; mt < 2; mt++) {
            int mr = m0 + wm * 32 + mt * 16 + g;
            float2 v0 = make_float2(acc[mt][nt][0] + bs0, acc[mt][nt][1] + bs1);
            float2 v1 = make_float2(acc[mt][nt][2] + bs0, acc[mt][nt][3] + bs1);
            *(float2*)(dst + (size_t)mr * G4 + r)       = v0;
            *(float2*)(dst + (size_t)(mr + 8) * G4 + r) = v1;
        }
    }
}

// ---------------------------------------------------------------------------
__device__ __forceinline__ float sigmoidf_(float x) {
    return __fdividef(1.f, 1.f + __expf(-x));
}
__device__ __forceinline__ float tanhf_(float x) {
    float e = __expf(-2.f * fabsf(x));
    float r = __fdividef(1.f - e, 1.f + e);
    return copysignf(r, x);
}

// Persistent bidirectional LSTM recurrence, FFMA2 (f32x2) matvec.
__global__ void __launch_bounds__(RTHREADS, 1) lstm_kernel(
    const float* __restrict__ whh,   // (2, 4H, H)
    float* __restrict__ seq_out,     // nullptr -> g_x1
    float* __restrict__ hn_out,
    float* __restrict__ cn_out,
    int layer)
{
    if (seq_out == nullptr) seq_out = g_x1;

    __shared__ float2 hsp[2][HID / 2];   // [parity][slot]: (h[64m+l], h[64m+32+l])

    int tid  = threadIdx.x;
    int warp = tid >> 5, lane = tid & 31;
    int dir  = blockIdx.x >> 6;
    int ub   = blockIdx.x & 63;
    int j    = ub * UPB + warp;

    // weights packed as f32x2 pairs matching hsp layout
    ull wp[4][12];
    #pragma unroll
    for (int gi = 0; gi < 4; gi++) {
        const float* rw = whh + ((size_t)dir * G4 + gi * HID + j) * HID;
        #pragma unroll
        for (int m = 0; m < 12; m++) {
            F2U w;
            w.f.x = rw[64 * m + lane];
            w.f.y = rw[64 * m + 32 + lane];
            wp[gi][m] = w.u;
        }
    }

    int s0   = ((warp >> 1) << 5) + lane;          // staging slot for h[tid]
    int s1   = (((warp + 12) >> 1) << 5) + lane;   // staging slot for h[tid+384]
    int comp = warp & 1;

    const float* preb = g_pre + (size_t)dir * TT * G4;
    const unsigned tagbase = (unsigned)(layer * TT);
    float c = 0.f;

    // prefetch pre-activations for t=0
    float xi, xf, xg, xo;
    {
        int tt = dir ? (TT - 1) : 0;
        const float* p = preb + (size_t)tt * G4;
        xi = __ldg(p + j); xf = __ldg(p + HID + j);
        xg = __ldg(p + 2 * HID + j); xo = __ldg(p + 3 * HID + j);
    }

    for (int t = 0; t < TT; ++t) {
        // prefetch pre for t+1 (issued before the poll to hide DRAM latency)
        float nxi = 0.f, nxf = 0.f, nxg = 0.f, nxo = 0.f;
        if (t + 1 < TT) {
            int tt2 = dir ? (TT - 2 - t) : (t + 1);
            const float* p2 = preb + (size_t)tt2 * G4;
            nxi = __ldg(p2 + j); nxf = __ldg(p2 + HID + j);
            nxg = __ldg(p2 + 2 * HID + j); nxo = __ldg(p2 + 3 * HID + j);
        }

        int b = t & 1;
        float* hpf = (float*)(&hsp[b][0]);
        if (t == 0) {
            hpf[s0 * 2 + comp] = 0.f;
            hpf[s1 * 2 + comp] = 0.f;
        } else {
            const ull* slot = &g_hb[(t - 1) & 1][dir][0];
            unsigned want = tagbase + (unsigned)t;       // tag of h_{t-1}
            ull v0 = ld_relaxed(slot + tid);
            while ((unsigned)(v0 >> 32) != want) v0 = ld_relaxed(slot + tid);
            ull v1 = ld_relaxed(slot + tid + 384);
            while ((unsigned)(v1 >> 32) != want) v1 = ld_relaxed(slot + tid + 384);
            hpf[s0 * 2 + comp] = __uint_as_float((unsigned)v0);
            hpf[s1 * 2 + comp] = __uint_as_float((unsigned)v1);
        }
        __syncthreads();   // single barrier per step (parity buffers)

        const ull* hv = (const ull*)(&hsp[b][0]);
        ull a0 = 0ull, a1 = 0ull, a2 = 0ull, a3 = 0ull;
        #pragma unroll
        for (int m = 0; m < 12; m++) {
            ull hm = hv[(m << 5) + lane];
            a0 = ffma2(wp[0][m], hm, a0);
            a1 = ffma2(wp[1][m], hm, a1);
            a2 = ffma2(wp[2][m], hm, a2);
            a3 = ffma2(wp[3][m], hm, a3);
        }
        F2U u0, u1, u2, u3;
        u0.u = a0; u1.u = a1; u2.u = a2; u3.u = a3;
        float r0 = u0.f.x + u0.f.y, r1 = u1.f.x + u1.f.y;
        float r2 = u2.f.x + u2.f.y, r3 = u3.f.x + u3.f.y;
        #pragma unroll
        for (int off = 16; off; off >>= 1) {
            r0 += __shfl_xor_sync(0xffffffffu, r0, off);
            r1 += __shfl_xor_sync(0xffffffffu, r1, off);
            r2 += __shfl_xor_sync(0xffffffffu, r2, off);
            r3 += __shfl_xor_sync(0xffffffffu, r3, off);
        }

        float ig = sigmoidf_(xi + r0);
        float fg = sigmoidf_(xf + r1);
        float gg = tanhf_(xg + r2);
        float og = sigmoidf_(xo + r3);
        c = fg * c + ig * gg;
        float h = og * tanhf_(c);

        if (lane == 0) {
            ull pk = ((ull)(tagbase + (unsigned)t + 1u) << 32) |
                     (ull)__float_as_uint(h);
            st_relaxed(&g_hb[t & 1][dir][j], pk);        // publish ASAP
            int tt = dir ? (TT - 1 - t) : t;
            seq_out[(size_t)tt * D2 + dir * HID + j] = h;
            if (t == TT - 1) {
                hn_out[(layer * 2 + dir) * HID + j] = h;
                cn_out[(layer * 2 + dir) * HID + j] = c;
            }
        }
        xi = nxi; xf = nxf; xg = nxg; xo = nxo;
    }
}

// ---------------------------------------------------------------------------
__global__ void sent_rep_kernel(const float* __restrict__ out,
                                const int* __restrict__ sep,
                                float* __restrict__ dst)
{
    int s = blockIdx.x;
    int st = sep[s], en = sep[s + 1];
    for (int i = threadIdx.x; i < D2; i += blockDim.x) {
        float v = (i < HID) ? out[(size_t)en * D2 + i] : out[(size_t)st * D2 + i];
        dst[(size_t)s * D2 + i] = v;
    }
}

__global__ void copy_rep_kernel(const float* __restrict__ out,
                                const int* __restrict__ comb_idx,
                                const int* __restrict__ comb_seg,
                                float* __restrict__ dst)
{
    int g = blockIdx.x;
    int lo = 0, hi = EE;
    while (lo < hi) { int m = (lo + hi) >> 1; if (comb_seg[m] <  g) lo = m + 1; else hi = m; }
    int st = lo;
    lo = st; hi = EE;
    while (lo < hi) { int m = (lo + hi) >> 1; if (comb_seg[m] <= g) lo = m + 1; else hi = m; }
    int en = lo;
    int n = en - st;
    float inv = 1.f / (float)(n > 0 ? n : 1);

    int cb = threadIdx.x;
    float acc[6] = {0.f, 0.f, 0.f, 0.f, 0.f, 0.f};
    for (int e = st; e < en; ++e) {
        const float* row = out + (size_t)comb_idx[e] * D2;
        #pragma unroll
        for (int q = 0; q < 6; q++) acc[q] += row[cb + q * 256];
    }
    #pragma unroll
    for (int q = 0; q < 6; q++)
        dst[(size_t)g * D2 + cb + q * 256] = acc[q] * inv;
}

// ---------------------------------------------------------------------------
extern "C" void kernel_launch(void* const* d_in, const int* in_sizes, int n_in,
                              void* d_out, int out_size)
{
    const float* input_t = (const float*)d_in[0];
    const float* w_ih0   = (const float*)d_in[1];
    const float* w_hh0   = (const float*)d_in[2];
    const float* b0      = (const float*)d_in[3];
    const float* w_ih1   = (const float*)d_in[4];
    const float* w_hh1   = (const float*)d_in[5];
    const float* b1      = (const float*)d_in[6];
    const int* comb_idx  = (const int*)d_in[7];
    const int* comb_seg  = (const int*)d_in[8];
    const int* sep       = (const int*)d_in[9];
    float* out = (float*)d_out;

    dim3 ggrid(48, 64);   // N=6144/128, M=8192/128

    init_kernel<<<12, 256>>>();
    gemm_pre_tc<<<ggrid, 256>>>(input_t, w_ih0, b0, 512);
    lstm_kernel<<<2 * NBD, RTHREADS>>>(w_hh0, nullptr,
                                       out + HN_OFF, out + CN_OFF, 0);
    init_kernel<<<12, 256>>>();
    gemm_pre_tc<<<ggrid, 256>>>(nullptr, w_ih1, b1, 1536);
    lstm_kernel<<<2 * NBD, RTHREADS>>>(w_hh1, out + OUT_OFF,
                                       out + HN_OFF, out + CN_OFF, 1);
    sent_rep_kernel<<<NSENT, 256>>>(out, sep, out + SENT_OFF);
    copy_rep_kernel<<<NG, 256>>>(out, comb_idx, comb_seg, out + COPY_OFF);
}

// round 5
// speedup vs baseline: 1.2840x; 1.2840x over previous
#include <cuda_runtime.h>

#define TT   8192
#define HID  768
#define G4   3072          // 4*HID
#define D2   1536          // 2*HID
#define EE   16384
#define NG   2048
#define NSENT 32

#define NBD      64        // blocks per direction
#define UPB      12        // hidden units per block
#define RTHREADS 384       // 12 warps: one warp per unit

// ---- output layout in d_out (flat float32, tuple order) ----
#define OUT_OFF  0
#define SENT_OFF (TT*D2)
#define COPY_OFF (SENT_OFF + NSENT*D2)
#define HN_OFF   (COPY_OFF + NG*D2)
#define CN_OFF   (HN_OFF + 4*HID)

typedef unsigned long long ull;

// ---- scratch ----
__device__ float g_pre[2ull * TT * G4];
__device__ float g_x1[(size_t)TT * D2];
__device__ ull   g_hb[2][2][HID];      // [parity][dir][unit]: (tag<<32)|bits(h)

// ---------------------------------------------------------------------------
__device__ __forceinline__ ull ld_relaxed(const ull* p) {
    ull v;
    asm volatile("ld.relaxed.gpu.global.b64 %0, [%1];" : "=l"(v) : "l"(p) : "memory");
    return v;
}
__device__ __forceinline__ void st_relaxed(ull* p, ull v) {
    asm volatile("st.relaxed.gpu.global.b64 [%0], %1;" :: "l"(p), "l"(v) : "memory");
}
__device__ __forceinline__ ull ffma2(ull a, ull b, ull c) {
    ull d;
    asm("fma.rn.f32x2 %0, %1, %2, %3;" : "=l"(d) : "l"(a), "l"(b), "l"(c));
    return d;
}
union F2U { float2 f; ull u; };

__global__ void init_kernel() {
    int tid = blockIdx.x * blockDim.x + threadIdx.x;
    if (tid < 2 * 2 * HID) ((ull*)g_hb)[tid] = 0ull;
}

// ---------------------------------------------------------------------------
// pre = X(M x K) @ W^T + bias -> g_pre[dir][t][4H]   (R2-proven SIMT GEMM)
__global__ __launch_bounds__(256, 2) void gemm_pre(
    const float* __restrict__ X,   // nullptr -> g_x1
    const float* __restrict__ W,   // (6144, K)
    const float* __restrict__ bias,
    int K)
{
    if (X == nullptr) X = g_x1;

    __shared__ float As[2][8][128];
    __shared__ float Bs[2][8][128];

    int tid = threadIdx.x;
    int tx = tid & 15, ty = tid >> 4;
    int m0 = blockIdx.y * 128, n0 = blockIdx.x * 128;

    int lr = tid >> 1;
    int lk = (tid & 1) * 4;

    const float* Ap = X + (size_t)(m0 + lr) * K + lk;
    const float* Bp = W + (size_t)(n0 + lr) * K + lk;

    float acc[8][8];
    #pragma unroll
    for (int i = 0; i < 8; i++)
        #pragma unroll
        for (int j = 0; j < 8; j++) acc[i][j] = 0.f;

    float4 a = *(const float4*)Ap;
    float4 b = *(const float4*)Bp;
    int buf = 0;

    for (int k0 = 0; k0 < K; k0 += 8) {
        As[buf][lk + 0][lr] = a.x; As[buf][lk + 1][lr] = a.y;
        As[buf][lk + 2][lr] = a.z; As[buf][lk + 3][lr] = a.w;
        Bs[buf][lk + 0][lr] = b.x; Bs[buf][lk + 1][lr] = b.y;
        Bs[buf][lk + 2][lr] = b.z; Bs[buf][lk + 3][lr] = b.w;
        __syncthreads();
        if (k0 + 8 < K) {
            a = *(const float4*)(Ap + k0 + 8);
            b = *(const float4*)(Bp + k0 + 8);
        }
        #pragma unroll
        for (int k = 0; k < 8; k++) {
            float ra[8], rb[8];
            *(float4*)(ra)     = *(const float4*)&As[buf][k][ty * 8];
            *(float4*)(ra + 4) = *(const float4*)&As[buf][k][ty * 8 + 4];
            *(float4*)(rb)     = *(const float4*)&Bs[buf][k][tx * 8];
            *(float4*)(rb + 4) = *(const float4*)&Bs[buf][k][tx * 8 + 4];
            #pragma unroll
            for (int i = 0; i < 8; i++)
                #pragma unroll
                for (int j = 0; j < 8; j++)
                    acc[i][j] = fmaf(ra[i], rb[j], acc[i][j]);
        }
        buf ^= 1;
    }

    int n_base = n0 + tx * 8;
    int d = (n_base >= G4) ? 1 : 0;
    int r0 = n_base - d * G4;
    float bn[8];
    #pragma unroll
    for (int j = 0; j < 8; j++) bn[j] = bias[n_base + j];
    float* dstbase = g_pre + (size_t)d * TT * G4 + r0;
    #pragma unroll
    for (int i = 0; i < 8; i++) {
        size_t t = (size_t)(m0 + ty * 8 + i);
        float4 v0 = make_float4(acc[i][0] + bn[0], acc[i][1] + bn[1],
                                acc[i][2] + bn[2], acc[i][3] + bn[3]);
        float4 v1 = make_float4(acc[i][4] + bn[4], acc[i][5] + bn[5],
                                acc[i][6] + bn[6], acc[i][7] + bn[7]);
        *(float4*)(dstbase + t * G4)     = v0;
        *(float4*)(dstbase + t * G4 + 4) = v1;
    }
}

// ---------------------------------------------------------------------------
__device__ __forceinline__ float sigmoidf_(float x) {
    return __fdividef(1.f, 1.f + __expf(-x));
}
__device__ __forceinline__ float tanhf_(float x) {
    float e = __expf(-2.f * fabsf(x));
    float r = __fdividef(1.f - e, 1.f + e);
    return copysignf(r, x);
}

// Persistent bidirectional LSTM recurrence.
// f32x2 matvec (pair layout), dual-issued polls, single barrier per step.
__global__ void __launch_bounds__(RTHREADS, 1) lstm_kernel(
    const float* __restrict__ whh,   // (2, 4H, H)
    float* __restrict__ seq_out,     // nullptr -> g_x1
    float* __restrict__ hn_out,
    float* __restrict__ cn_out,
    int layer)
{
    if (seq_out == nullptr) seq_out = g_x1;

    __shared__ __align__(16) float hs[2][HID];   // parity double buffer

    int tid  = threadIdx.x;
    int warp = tid >> 5, lane = tid & 31;
    int dir  = blockIdx.x >> 6;
    int ub   = blockIdx.x & 63;
    int j    = ub * UPB + warp;

    // weights as f32x2 pairs: wp[g][m] = (W[row][64m+2*lane], W[row][64m+2*lane+1])
    ull wp[4][12];
    #pragma unroll
    for (int g = 0; g < 4; g++) {
        const float* rw = whh + ((size_t)dir * G4 + g * HID + j) * HID + 2 * lane;
        #pragma unroll
        for (int m = 0; m < 12; m++) {
            F2U w;
            w.f = *(const float2*)(rw + 64 * m);
            wp[g][m] = w.u;
        }
    }

    const float* preb = g_pre + (size_t)dir * TT * G4;
    const unsigned tagbase = (unsigned)(layer * TT);
    float c = 0.f;

    for (int t = 0; t < TT; ++t) {
        int tt = dir ? (TT - 1 - t) : t;
        const float* p = preb + (size_t)tt * G4;
        // pre-activation loads issued before the poll (hide DRAM latency)
        float xi = __ldg(p + j);
        float xf = __ldg(p + HID + j);
        float xg = __ldg(p + 2 * HID + j);
        float xo = __ldg(p + 3 * HID + j);

        float* hb = hs[t & 1];
        if (t == 0) {
            hb[tid] = 0.f; hb[tid + 384] = 0.f;
        } else {
            const ull* slot = &g_hb[(t - 1) & 1][dir][0];
            unsigned want = tagbase + (unsigned)t;   // tag of h_{t-1}
            // issue BOTH loads before either spin
            ull v0 = ld_relaxed(slot + tid);
            ull v1 = ld_relaxed(slot + tid + 384);
            while ((unsigned)(v0 >> 32) != want) v0 = ld_relaxed(slot + tid);
            while ((unsigned)(v1 >> 32) != want) v1 = ld_relaxed(slot + tid + 384);
            hb[tid]       = __uint_as_float((unsigned)v0);
            hb[tid + 384] = __uint_as_float((unsigned)v1);
        }
        __syncthreads();   // single barrier per step

        const ull* hv = (const ull*)hb;        // float2 pairs, natural order
        ull a0 = 0ull, a1 = 0ull, a2 = 0ull, a3 = 0ull;
        #pragma unroll
        for (int m = 0; m < 12; m++) {
            ull hm = hv[(m << 5) + lane];      // h[64m+2lane], h[64m+2lane+1]
            a0 = ffma2(wp[0][m], hm, a0);
            a1 = ffma2(wp[1][m], hm, a1);
            a2 = ffma2(wp[2][m], hm, a2);
            a3 = ffma2(wp[3][m], hm, a3);
        }
        F2U u0, u1, u2, u3;
        u0.u = a0; u1.u = a1; u2.u = a2; u3.u = a3;
        float r0 = u0.f.x + u0.f.y, r1 = u1.f.x + u1.f.y;
        float r2 = u2.f.x + u2.f.y, r3 = u3.f.x + u3.f.y;
        #pragma unroll
        for (int off = 16; off; off >>= 1) {
            r0 += __shfl_xor_sync(0xffffffffu, r0, off);
            r1 += __shfl_xor_sync(0xffffffffu, r1, off);
            r2 += __shfl_xor_sync(0xffffffffu, r2, off);
            r3 += __shfl_xor_sync(0xffffffffu, r3, off);
        }

        float ig = sigmoidf_(xi + r0);
        float fg = sigmoidf_(xf + r1);
        float gg = tanhf_(xg + r2);
        float og = sigmoidf_(xo + r3);
        c = fg * c + ig * gg;
        float h = og * tanhf_(c);

        if (lane == 0) {
            ull pk = ((ull)(tagbase + (unsigned)t + 1u) << 32) |
                     (ull)__float_as_uint(h);
            st_relaxed(&g_hb[t & 1][dir][j], pk);        // publish ASAP
            seq_out[(size_t)tt * D2 + dir * HID + j] = h;
            if (t == TT - 1) {
                hn_out[(layer * 2 + dir) * HID + j] = h;
                cn_out[(layer * 2 + dir) * HID + j] = c;
            }
        }
        // no trailing barrier: next step stages into the other parity buffer
    }
}

// ---------------------------------------------------------------------------
__global__ void sent_rep_kernel(const float* __restrict__ out,
                                const int* __restrict__ sep,
                                float* __restrict__ dst)
{
    int s = blockIdx.x;
    int st = sep[s], en = sep[s + 1];
    for (int i = threadIdx.x; i < D2; i += blockDim.x) {
        float v = (i < HID) ? out[(size_t)en * D2 + i] : out[(size_t)st * D2 + i];
        dst[(size_t)s * D2 + i] = v;
    }
}

__global__ void copy_rep_kernel(const float* __restrict__ out,
                                const int* __restrict__ comb_idx,
                                const int* __restrict__ comb_seg,
                                float* __restrict__ dst)
{
    int g = blockIdx.x;
    int lo = 0, hi = EE;
    while (lo < hi) { int m = (lo + hi) >> 1; if (comb_seg[m] <  g) lo = m + 1; else hi = m; }
    int st = lo;
    lo = st; hi = EE;
    while (lo < hi) { int m = (lo + hi) >> 1; if (comb_seg[m] <= g) lo = m + 1; else hi = m; }
    int en = lo;
    int n = en - st;
    float inv = 1.f / (float)(n > 0 ? n : 1);

    int cb = threadIdx.x;
    float acc[6] = {0.f, 0.f, 0.f, 0.f, 0.f, 0.f};
    for (int e = st; e < en; ++e) {
        const float* row = out + (size_t)comb_idx[e] * D2;
        #pragma unroll
        for (int q = 0; q < 6; q++) acc[q] += row[cb + q * 256];
    }
    #pragma unroll
    for (int q = 0; q < 6; q++)
        dst[(size_t)g * D2 + cb + q * 256] = acc[q] * inv;
}

// ---------------------------------------------------------------------------
extern "C" void kernel_launch(void* const* d_in, const int* in_sizes, int n_in,
                              void* d_out, int out_size)
{
    const float* input_t = (const float*)d_in[0];
    const float* w_ih0   = (const float*)d_in[1];
    const float* w_hh0   = (const float*)d_in[2];
    const float* b0      = (const float*)d_in[3];
    const float* w_ih1   = (const float*)d_in[4];
    const float* w_hh1   = (const float*)d_in[5];
    const float* b1      = (const float*)d_in[6];
    const int* comb_idx  = (const int*)d_in[7];
    const int* comb_seg  = (const int*)d_in[8];
    const int* sep       = (const int*)d_in[9];
    float* out = (float*)d_out;

    dim3 ggrid(48, 64);   // N=6144/128, M=8192/128

    init_kernel<<<12, 256>>>();
    gemm_pre<<<ggrid, 256>>>(input_t, w_ih0, b0, 512);
    lstm_kernel<<<2 * NBD, RTHREADS>>>(w_hh0, nullptr,
                                       out + HN_OFF, out + CN_OFF, 0);
    init_kernel<<<12, 256>>>();
    gemm_pre<<<ggrid, 256>>>(nullptr, w_ih1, b1, 1536);
    lstm_kernel<<<2 * NBD, RTHREADS>>>(w_hh1, out + OUT_OFF,
                                       out + HN_OFF, out + CN_OFF, 1);
    sent_rep_kernel<<<NSENT, 256>>>(out, sep, out + SENT_OFF);
    copy_rep_kernel<<<NG, 256>>>(out, comb_idx, comb_seg, out + COPY_OFF);
}

// round 6
// speedup vs baseline: 1.8821x; 1.4658x over previous
#include <cuda_runtime.h>

#define TT   8192
#define HID  768
#define G4   3072          // 4*HID
#define D2   1536          // 2*HID
#define EE   16384
#define NG   2048
#define NSENT 32

#define NBD      64        // blocks per direction
#define UPB      12        // hidden units per block
#define RTHREADS 384       // 12 warps: one warp per unit

// ---- output layout in d_out (flat float32, tuple order) ----
#define OUT_OFF  0
#define SENT_OFF (TT*D2)
#define COPY_OFF (SENT_OFF + NSENT*D2)
#define HN_OFF   (COPY_OFF + NG*D2)
#define CN_OFF   (HN_OFF + 4*HID)

typedef unsigned long long ull;

// ---- scratch ----
__device__ float g_pre[2ull * TT * G4];
__device__ float g_x1[(size_t)TT * D2];
__device__ ull   g_hb[2][2][HID];      // [parity][dir][unit]: (tag<<32)|bits(h)
// NOTE: no init kernel. Tags are disjoint across layers AND across graph
// replays: layer-0 polls want tags 1..8191 while stale slots hold layer-1
// tags 8194..16384 from the previous replay; layer-1 polls want >=8193 while
// same-replay layer-0 wrote <=8192. First call sees zero-initialized globals.

// ---------------------------------------------------------------------------
__device__ __forceinline__ ull ld_relaxed(const ull* p) {
    ull v;
    asm volatile("ld.relaxed.gpu.global.b64 %0, [%1];" : "=l"(v) : "l"(p) : "memory");
    return v;
}
__device__ __forceinline__ void st_relaxed(ull* p, ull v) {
    asm volatile("st.relaxed.gpu.global.b64 [%0], %1;" :: "l"(p), "l"(v) : "memory");
}

// ---------------------------------------------------------------------------
// pre = X(M x K) @ W^T + bias -> g_pre[dir][t][4H]
// 128x128x16 SIMT SGEMM, double-buffered, 1 barrier per 16-k tile, 2 CTAs/SM.
__global__ __launch_bounds__(256, 2) void gemm_pre(
    const float* __restrict__ X,   // nullptr -> g_x1
    const float* __restrict__ W,   // (6144, K)
    const float* __restrict__ bias,
    int K)
{
    if (X == nullptr) X = g_x1;

    __shared__ float As[2][16][128];
    __shared__ float Bs[2][16][128];

    int tid = threadIdx.x;
    int tx = tid & 15, ty = tid >> 4;
    int m0 = blockIdx.y * 128, n0 = blockIdx.x * 128;

    int lr = tid >> 1;            // 0..127: row within tile
    int lk = (tid & 1) * 8;       // 0 or 8: k-offset within 16-k tile

    const float* Ap = X + (size_t)(m0 + lr) * K + lk;
    const float* Bp = W + (size_t)(n0 + lr) * K + lk;

    float acc[8][8];
    #pragma unroll
    for (int i = 0; i < 8; i++)
        #pragma unroll
        for (int j = 0; j < 8; j++) acc[i][j] = 0.f;

    float4 a0 = *(const float4*)(Ap);
    float4 a1 = *(const float4*)(Ap + 4);
    float4 b0 = *(const float4*)(Bp);
    float4 b1 = *(const float4*)(Bp + 4);
    int buf = 0;

    for (int k0 = 0; k0 < K; k0 += 16) {
        As[buf][lk + 0][lr] = a0.x; As[buf][lk + 1][lr] = a0.y;
        As[buf][lk + 2][lr] = a0.z; As[buf][lk + 3][lr] = a0.w;
        As[buf][lk + 4][lr] = a1.x; As[buf][lk + 5][lr] = a1.y;
        As[buf][lk + 6][lr] = a1.z; As[buf][lk + 7][lr] = a1.w;
        Bs[buf][lk + 0][lr] = b0.x; Bs[buf][lk + 1][lr] = b0.y;
        Bs[buf][lk + 2][lr] = b0.z; Bs[buf][lk + 3][lr] = b0.w;
        Bs[buf][lk + 4][lr] = b1.x; Bs[buf][lk + 5][lr] = b1.y;
        Bs[buf][lk + 6][lr] = b1.z; Bs[buf][lk + 7][lr] = b1.w;
        __syncthreads();
        if (k0 + 16 < K) {                  // prefetch next tile
            a0 = *(const float4*)(Ap + k0 + 16);
            a1 = *(const float4*)(Ap + k0 + 20);
            b0 = *(const float4*)(Bp + k0 + 16);
            b1 = *(const float4*)(Bp + k0 + 20);
        }
        #pragma unroll
        for (int k = 0; k < 16; k++) {
            float ra[8], rb[8];
            *(float4*)(ra)     = *(const float4*)&As[buf][k][ty * 8];
            *(float4*)(ra + 4) = *(const float4*)&As[buf][k][ty * 8 + 4];
            *(float4*)(rb)     = *(const float4*)&Bs[buf][k][tx * 8];
            *(float4*)(rb + 4) = *(const float4*)&Bs[buf][k][tx * 8 + 4];
            #pragma unroll
            for (int i = 0; i < 8; i++)
                #pragma unroll
                for (int j = 0; j < 8; j++)
                    acc[i][j] = fmaf(ra[i], rb[j], acc[i][j]);
        }
        buf ^= 1;
    }

    int n_base = n0 + tx * 8;
    int d = (n_base >= G4) ? 1 : 0;
    int r0 = n_base - d * G4;
    float bn[8];
    #pragma unroll
    for (int j = 0; j < 8; j++) bn[j] = bias[n_base + j];
    float* dstbase = g_pre + (size_t)d * TT * G4 + r0;
    #pragma unroll
    for (int i = 0; i < 8; i++) {
        size_t t = (size_t)(m0 + ty * 8 + i);
        float4 v0 = make_float4(acc[i][0] + bn[0], acc[i][1] + bn[1],
                                acc[i][2] + bn[2], acc[i][3] + bn[3]);
        float4 v1 = make_float4(acc[i][4] + bn[4], acc[i][5] + bn[5],
                                acc[i][6] + bn[6], acc[i][7] + bn[7]);
        *(float4*)(dstbase + t * G4)     = v0;
        *(float4*)(dstbase + t * G4 + 4) = v1;
    }
}

// ---------------------------------------------------------------------------
__device__ __forceinline__ float sigmoidf_(float x) {
    return __fdividef(1.f, 1.f + __expf(-x));
}
__device__ __forceinline__ float tanhf_(float x) {
    float e = __expf(-2.f * fabsf(x));
    float r = __fdividef(1.f - e, 1.f + e);
    return copysignf(r, x);
}

// Persistent bidirectional LSTM recurrence (R2-proven structure; the only
// change vs R2 is issuing both poll loads before either spin).
__global__ void __launch_bounds__(RTHREADS, 1) lstm_kernel(
    const float* __restrict__ whh,   // (2, 4H, H)
    float* __restrict__ seq_out,     // nullptr -> g_x1
    float* __restrict__ hn_out,
    float* __restrict__ cn_out,
    int layer)
{
    if (seq_out == nullptr) seq_out = g_x1;

    __shared__ float hs[HID];

    int tid  = threadIdx.x;
    int warp = tid >> 5, lane = tid & 31;
    int dir  = blockIdx.x >> 6;
    int ub   = blockIdx.x & 63;
    int j    = ub * UPB + warp;

    const float* wbase = whh + ((size_t)dir * G4 + j) * HID + lane;
    const int GSTRIDE = HID * HID;
    float w0[24], w1[24], w2[24], w3[24];
    #pragma unroll
    for (int k = 0; k < 24; k++) {
        int c = 32 * k;
        w0[k] = wbase[0 * GSTRIDE + c];
        w1[k] = wbase[1 * GSTRIDE + c];
        w2[k] = wbase[2 * GSTRIDE + c];
        w3[k] = wbase[3 * GSTRIDE + c];
    }

    const float* preb = g_pre + (size_t)dir * TT * G4;
    const unsigned tagbase = (unsigned)(layer * TT);
    float c = 0.f;

    for (int t = 0; t < TT; ++t) {
        int tt = dir ? (TT - 1 - t) : t;
        const float* p = preb + (size_t)tt * G4;
        float xi = __ldg(p + j);
        float xf = __ldg(p + HID + j);
        float xg = __ldg(p + 2 * HID + j);
        float xo = __ldg(p + 3 * HID + j);

        if (t == 0) {
            hs[tid] = 0.f; hs[tid + 384] = 0.f;
        } else {
            const ull* slot = &g_hb[(t - 1) & 1][dir][0];
            unsigned want = tagbase + (unsigned)t;
            // issue BOTH loads before either spin (one L2 round trip, not two)
            ull v0 = ld_relaxed(slot + tid);
            ull v1 = ld_relaxed(slot + tid + 384);
            while ((unsigned)(v0 >> 32) != want) v0 = ld_relaxed(slot + tid);
            while ((unsigned)(v1 >> 32) != want) v1 = ld_relaxed(slot + tid + 384);
            hs[tid]       = __uint_as_float((unsigned)v0);
            hs[tid + 384] = __uint_as_float((unsigned)v1);
        }
        __syncthreads();

        float a0 = 0.f, a1 = 0.f, a2 = 0.f, a3 = 0.f;
        #pragma unroll
        for (int k = 0; k < 24; k++) {
            float hk = hs[32 * k + lane];
            a0 = fmaf(w0[k], hk, a0);
            a1 = fmaf(w1[k], hk, a1);
            a2 = fmaf(w2[k], hk, a2);
            a3 = fmaf(w3[k], hk, a3);
        }
        #pragma unroll
        for (int off = 16; off; off >>= 1) {
            a0 += __shfl_xor_sync(0xffffffffu, a0, off);
            a1 += __shfl_xor_sync(0xffffffffu, a1, off);
            a2 += __shfl_xor_sync(0xffffffffu, a2, off);
            a3 += __shfl_xor_sync(0xffffffffu, a3, off);
        }

        float ig = sigmoidf_(xi + a0);
        float fg = sigmoidf_(xf + a1);
        float gg = tanhf_(xg + a2);
        float og = sigmoidf_(xo + a3);
        c = fg * c + ig * gg;
        float h = og * tanhf_(c);

        if (lane == 0) {
            ull pk = ((ull)(tagbase + (unsigned)t + 1u) << 32) |
                     (ull)__float_as_uint(h);
            st_relaxed(&g_hb[t & 1][dir][j], pk);
            seq_out[(size_t)tt * D2 + dir * HID + j] = h;
            if (t == TT - 1) {
                hn_out[(layer * 2 + dir) * HID + j] = h;
                cn_out[(layer * 2 + dir) * HID + j] = c;
            }
        }
        __syncthreads();
    }
}

// ---------------------------------------------------------------------------
__global__ void sent_rep_kernel(const float* __restrict__ out,
                                const int* __restrict__ sep,
                                float* __restrict__ dst)
{
    int s = blockIdx.x;
    int st = sep[s], en = sep[s + 1];
    for (int i = threadIdx.x; i < D2; i += blockDim.x) {
        float v = (i < HID) ? out[(size_t)en * D2 + i] : out[(size_t)st * D2 + i];
        dst[(size_t)s * D2 + i] = v;
    }
}

__global__ void copy_rep_kernel(const float* __restrict__ out,
                                const int* __restrict__ comb_idx,
                                const int* __restrict__ comb_seg,
                                float* __restrict__ dst)
{
    int g = blockIdx.x;
    int lo = 0, hi = EE;
    while (lo < hi) { int m = (lo + hi) >> 1; if (comb_seg[m] <  g) lo = m + 1; else hi = m; }
    int st = lo;
    lo = st; hi = EE;
    while (lo < hi) { int m = (lo + hi) >> 1; if (comb_seg[m] <= g) lo = m + 1; else hi = m; }
    int en = lo;
    int n = en - st;
    float inv = 1.f / (float)(n > 0 ? n : 1);

    int cb = threadIdx.x;
    float acc[6] = {0.f, 0.f, 0.f, 0.f, 0.f, 0.f};
    for (int e = st; e < en; ++e) {
        const float* row = out + (size_t)comb_idx[e] * D2;
        #pragma unroll
        for (int q = 0; q < 6; q++) acc[q] += row[cb + q * 256];
    }
    #pragma unroll
    for (int q = 0; q < 6; q++)
        dst[(size_t)g * D2 + cb + q * 256] = acc[q] * inv;
}

// ---------------------------------------------------------------------------
extern "C" void kernel_launch(void* const* d_in, const int* in_sizes, int n_in,
                              void* d_out, int out_size)
{
    const float* input_t = (const float*)d_in[0];
    const float* w_ih0   = (const float*)d_in[1];
    const float* w_hh0   = (const float*)d_in[2];
    const float* b0      = (const float*)d_in[3];
    const float* w_ih1   = (const float*)d_in[4];
    const float* w_hh1   = (const float*)d_in[5];
    const float* b1      = (const float*)d_in[6];
    const int* comb_idx  = (const int*)d_in[7];
    const int* comb_seg  = (const int*)d_in[8];
    const int* sep       = (const int*)d_in[9];
    float* out = (float*)d_out;

    dim3 ggrid(48, 64);   // N=6144/128, M=8192/128

    gemm_pre<<<ggrid, 256>>>(input_t, w_ih0, b0, 512);
    lstm_kernel<<<2 * NBD, RTHREADS>>>(w_hh0, nullptr,
                                       out + HN_OFF, out + CN_OFF, 0);
    gemm_pre<<<ggrid, 256>>>(nullptr, w_ih1, b1, 1536);
    lstm_kernel<<<2 * NBD, RTHREADS>>>(w_hh1, out + OUT_OFF,
                                       out + HN_OFF, out + CN_OFF, 1);
    sent_rep_kernel<<<NSENT, 256>>>(out, sep, out + SENT_OFF);
    copy_rep_kernel<<<NG, 256>>>(out, comb_idx, comb_seg, out + COPY_OFF);
}